// round 16
// baseline (speedup 1.0000x reference)
#include <cuda_runtime.h>
#include <cuda_fp16.h>
#include <math.h>

#define B_ 32
#define L_ 64
#define H_ 1024
#define E_ 8
#define V_ 12000
#define OUT_ 16
#define HID_ 512
#define COMP_OFF 512                 // gauss_param occupies out[0:512]
#define LOSS_OFF (512 + 32*64*12000) // scalar at the end
#define NVT 94                       // ceil(12000/128)
#define NJOBS 16                     // max sum_e ceil(n_e/4), sum n_e = 32

// -------------------- scratch (static device globals only) -----------------
__device__ float  g_hid[B_ * HID_];
__device__ int2   g_sel[B_];
__device__ float2 g_gate[B_];
__device__ __half g_h16[B_ * 2 * L_ * H_];   // [b][ei][l][k], gate pre-folded
// expert-grouped job tables, one per pass (built by k_gate thread 0)
__device__ int    g_job_e[2][NJOBS];
__device__ int    g_job_nb[2][NJOBS];
__device__ int    g_job_b[2][NJOBS * 4];

// ===================== PTX helpers (all plain sm_80+ PTX) ==================
__device__ __forceinline__ unsigned smem_u32(const void* p) {
    unsigned a;
    asm("{ .reg .u64 t; cvta.to.shared.u64 t, %1; cvt.u32.u64 %0, t; }"
        : "=r"(a) : "l"(p));
    return a;
}
__device__ __forceinline__ void cp16(unsigned d, const void* s) {
    asm volatile("cp.async.cg.shared.global [%0], [%1], 16;"
                 :: "r"(d), "l"(s) : "memory");
}
__device__ __forceinline__ void sts128(unsigned a, unsigned x, unsigned y,
                                       unsigned z, unsigned w) {
    asm volatile("st.shared.v4.b32 [%0], {%1,%2,%3,%4};"
                 :: "r"(a), "r"(x), "r"(y), "r"(z), "r"(w) : "memory");
}
__device__ __forceinline__ void ldm_x4(unsigned& r0, unsigned& r1,
                                       unsigned& r2, unsigned& r3, unsigned a) {
    asm volatile("ldmatrix.sync.aligned.m8n8.x4.shared.b16 {%0,%1,%2,%3}, [%4];"
                 : "=r"(r0), "=r"(r1), "=r"(r2), "=r"(r3) : "r"(a));
}
__device__ __forceinline__ void mma16816(float& c0, float& c1, float& c2, float& c3,
                                         unsigned a0, unsigned a1, unsigned a2,
                                         unsigned a3, unsigned b0, unsigned b1) {
    asm volatile(
        "mma.sync.aligned.m16n8k16.row.col.f32.f16.f16.f32 "
        "{%0,%1,%2,%3}, {%4,%5,%6,%7}, {%8,%9}, {%0,%1,%2,%3};"
        : "+f"(c0), "+f"(c1), "+f"(c2), "+f"(c3)
        : "r"(a0), "r"(a1), "r"(a2), "r"(a3), "r"(b0), "r"(b1));
}
__device__ __forceinline__ unsigned h2u(__half2 h) {
    return *reinterpret_cast<unsigned*>(&h);
}
#define SWZ(o) ((o) ^ (((o) >> 3) & 0x70))

// SMEM: A = W f16 [128v x 64k] x2 buffers; B = h f16 [64l x 64k] x2 x 4 b's
#define SM_A0   0
#define SM_A1   16384
#define SM_B(buf, bb) (32768 + (buf) * 32768 + (bb) * 8192)
#define SMEM_TOTAL 98304

// -------------------- K1: hid = relu(q @ w1 + b1) --------------------------
__global__ void k_hid(const float* __restrict__ q,
                      const float* __restrict__ w1,
                      const float* __restrict__ b1) {
    __shared__ float qs[H_];
    int b = blockIdx.x;
    int j = blockIdx.y * 128 + threadIdx.x;
    for (int i = threadIdx.x; i < H_; i += 128) qs[i] = q[b * H_ + i];
    __syncthreads();
    float acc = b1[j];
#pragma unroll 8
    for (int i = 0; i < H_; ++i) acc = fmaf(qs[i], w1[i * HID_ + j], acc);
    g_hid[b * HID_ + j] = fmaxf(acc, 0.0f);
}

// -------- K2: logits, top-2 gates, moe_loss, per-pass job tables -----------
__global__ void k_gate(const float* __restrict__ w2,
                       const float* __restrict__ b2,
                       float* __restrict__ out) {
    __shared__ float w2s[HID_ * E_];
    __shared__ float lg[B_ * E_];
    __shared__ float gd[B_ * E_];
    __shared__ float imp[E_];
    int t = threadIdx.x;
    for (int i = t; i < HID_ * E_; i += 256) w2s[i] = w2[i];
    gd[t] = 0.0f;
    __syncthreads();
    {
        int b = t >> 3, e = t & 7;
        float acc = b2[e];
        const float* hb = &g_hid[b * HID_];
#pragma unroll 8
        for (int i = 0; i < HID_; ++i) acc = fmaf(hb[i], w2s[i * E_ + e], acc);
        lg[t] = acc;
    }
    __syncthreads();
    if (t < B_) {
        float v1 = -1e30f, v2 = -1e30f;
        int i1 = 0, i2 = 0;
        for (int e = 0; e < E_; ++e) {
            float v = lg[t * E_ + e];
            if (v > v1)      { v2 = v1; i2 = i1; v1 = v; i1 = e; }
            else if (v > v2) { v2 = v;  i2 = e; }
        }
        float ex = expf(v2 - v1);
        float s = 1.0f + ex;
        float g1 = 1.0f / s, g2 = ex / s;
        g_sel[t] = make_int2(i1, i2);
        g_gate[t] = make_float2(g1, g2);
        gd[t * E_ + i1] = g1;
        gd[t * E_ + i2] = g2;
    }
    __syncthreads();
    if (t < E_) {
        float s = 0.0f;
        for (int b = 0; b < B_; ++b) s += gd[b * E_ + t];
        imp[t] = s;
    }
    __syncthreads();
    if (t == 0) {
        float mean = 0.0f;
        for (int e = 0; e < E_; ++e) mean += imp[e];
        mean *= (1.0f / E_);
        float var = 0.0f;
        for (int e = 0; e < E_; ++e) { float d = imp[e] - mean; var += d * d; }
        var *= (1.0f / (E_ - 1));
        out[LOSS_OFF] = sqrtf(var) / (mean + 1e-10f) * 0.1f;

        // ---- per-pass expert-grouped jobs (<=4 b's per job) ----
        for (int pass = 0; pass < 2; ++pass) {
            int nj = 0;
            for (int e = 0; e < E_; ++e) {
                int cb[4], cnt = 0;
                for (int b = 0; b < B_; ++b) {
                    int se = pass ? g_sel[b].y : g_sel[b].x;
                    if (se != e) continue;
                    cb[cnt++] = b;
                    if (cnt == 4) {
                        g_job_e[pass][nj] = e; g_job_nb[pass][nj] = 4;
                        for (int i2 = 0; i2 < 4; ++i2)
                            g_job_b[pass][nj * 4 + i2] = cb[i2];
                        ++nj; cnt = 0;
                    }
                }
                if (cnt > 0) {
                    g_job_e[pass][nj] = e; g_job_nb[pass][nj] = cnt;
                    for (int i2 = 0; i2 < cnt; ++i2)
                        g_job_b[pass][nj * 4 + i2] = cb[i2];
                    ++nj;
                }
            }
            for (; nj < NJOBS; ++nj) g_job_nb[pass][nj] = 0;
        }
    }
}

// -------- K2.5: prescale h by gate, round to f16 ---------------------------
__global__ void k_prep(const float* __restrict__ h) {
    int b = blockIdx.x, ei = blockIdx.y;
    float g = ei ? g_gate[b].y : g_gate[b].x;
    const float4* src = (const float4*)(h + (size_t)b * L_ * H_);
    __half2* dst = (__half2*)(g_h16 + ((size_t)(b * 2 + ei)) * L_ * H_);
    for (int i = threadIdx.x; i < L_ * H_ / 4; i += 256) {
        float4 v = src[i];
        dst[2 * i + 0] = __floats2half2_rn(g * v.x, g * v.y);
        dst[2 * i + 1] = __floats2half2_rn(g * v.z, g * v.w);
    }
}

// -------- K3: gauss_param = sigmoid(h_last . mixed_w + mixed_b) ------------
__global__ void k_gauss(const float* __restrict__ h,
                        const float* __restrict__ gw,
                        const float* __restrict__ gb,
                        float* __restrict__ out) {
    __shared__ float part[2];
    int b = blockIdx.x, o = blockIdx.y;
    int w = threadIdx.x >> 5, l = threadIdx.x & 31;
    int2 sel = g_sel[b];
    float2 gg = g_gate[b];
    int e = w ? sel.y : sel.x;
    float g = w ? gg.y : gg.x;
    const float* hl = h + ((size_t)b * L_ + (L_ - 1)) * H_;
    const float* wp = gw + ((size_t)e * OUT_ + o) * H_;
    float a = 0.0f;
#pragma unroll 8
    for (int i = l; i < H_; i += 32) a = fmaf(hl[i], wp[i], a);
#pragma unroll
    for (int off = 16; off > 0; off >>= 1)
        a += __shfl_down_sync(0xffffffff, a, off);
    if (l == 0) part[w] = g * (a + gb[e * OUT_ + o]);
    __syncthreads();
    if (threadIdx.x == 0) {
        float val = part[0] + part[1];
        out[b * OUT_ + o] = 1.0f / (1.0f + expf(-val));
    }
}

// -------- K4: comp via expert-grouped HMMA jobs, two passes ----------------
// PASS 0: sel.x slots, plain store of acc + full mixed bias.
// PASS 1: sel.y slots, out += acc (each element owned by exactly one job per
// pass; stream order serializes the passes). Zero atomics.
template <int NB, int PASS>
__device__ __forceinline__ void comp_body(const float* __restrict__ comp_w,
                                          const float* __restrict__ comp_b,
                                          float* __restrict__ out,
                                          unsigned sb, int job, int vbase) {
    const int t = threadIdx.x, wid = t >> 5, lane = t & 31;
    const int warp_m = wid >> 2, warp_n = wid & 3;
    const int e = g_job_e[PASS][job];

    int jb[NB];
#pragma unroll
    for (int bi = 0; bi < NB; ++bi) jb[bi] = g_job_b[PASS][job * 4 + bi];

    float c[NB][2][2][4];
#pragma unroll
    for (int bi = 0; bi < NB; ++bi)
#pragma unroll
        for (int i = 0; i < 2; ++i)
#pragma unroll
            for (int j = 0; j < 2; ++j)
#pragma unroll
                for (int k = 0; k < 4; ++k) c[bi][i][j][k] = 0.0f;

    // ---- prologue: cp.async h(0) for all NB (1 cp16/thread/b) ----
#pragma unroll
    for (int bi = 0; bi < NB; ++bi) {
        const __half* src = g_h16 + (size_t)(jb[bi] * 2 + PASS) * L_ * H_;
        int r = t >> 3, cc = t & 7;
        cp16(sb + SM_B(0, bi) + SWZ(r * 128 + cc * 16), src + r * H_ + cc * 8);
    }
    asm volatile("cp.async.commit_group;" ::: "memory");

    const float* We = comp_w + (size_t)e * V_ * H_;
    float4 wreg[4];
#pragma unroll
    for (int j = 0; j < 2; ++j) {
        int tau = t + 512 * j, r = tau >> 3, cc = tau & 7;
        int v = vbase + r; if (v >= V_) v = V_ - 1;
        const float4* p = (const float4*)(We + (size_t)v * H_ + cc * 8);
        wreg[2 * j] = p[0]; wreg[2 * j + 1] = p[1];
    }

    const int a_row = warp_m * 32 + (lane & 7) + ((lane >> 3) & 1) * 8;
    const int a_kb  = ((lane >> 4) & 1) * 16;
    const int b_row = warp_n * 16 + (lane & 7) + ((lane >> 4) & 1) * 8;
    const int b_kb  = ((lane >> 3) & 1) * 16;

    for (int s = 0; s < 16; ++s) {
        const unsigned Ab = sb + ((s & 1) ? SM_A1 : SM_A0);

        asm volatile("cp.async.wait_group 0;" ::: "memory");

        // store W(s) as f16 (other buffer than compute(s-1) reads)
#pragma unroll
        for (int j = 0; j < 2; ++j) {
            int tau = t + 512 * j, r = tau >> 3, cc = tau & 7;
            __half2 h0 = __floats2half2_rn(wreg[2 * j].x,     wreg[2 * j].y);
            __half2 h1 = __floats2half2_rn(wreg[2 * j].z,     wreg[2 * j].w);
            __half2 h2 = __floats2half2_rn(wreg[2 * j + 1].x, wreg[2 * j + 1].y);
            __half2 h3 = __floats2half2_rn(wreg[2 * j + 1].z, wreg[2 * j + 1].w);
            sts128(Ab + SWZ(r * 128 + cc * 16), h2u(h0), h2u(h1), h2u(h2), h2u(h3));
        }

        if (s + 1 < 16) {
            int k0 = (s + 1) * 64;
#pragma unroll
            for (int j = 0; j < 2; ++j) {
                int tau = t + 512 * j, r = tau >> 3, cc = tau & 7;
                int v = vbase + r; if (v >= V_) v = V_ - 1;
                const float4* p = (const float4*)(We + (size_t)v * H_ + k0 + cc * 8);
                wreg[2 * j] = p[0]; wreg[2 * j + 1] = p[1];
            }
        }

        __syncthreads();

        if (s + 1 < 16) {
            int k0 = (s + 1) * 64, buf = (s + 1) & 1;
#pragma unroll
            for (int bi = 0; bi < NB; ++bi) {
                const __half* src =
                    g_h16 + (size_t)(jb[bi] * 2 + PASS) * L_ * H_ + k0;
                int r = t >> 3, cc = t & 7;
                cp16(sb + SM_B(buf, bi) + SWZ(r * 128 + cc * 16),
                     src + r * H_ + cc * 8);
            }
            asm volatile("cp.async.commit_group;" ::: "memory");
        }

        // ---- compute: 4 k-steps; A ldm shared across all NB b's ----
#pragma unroll
        for (int ks = 0; ks < 4; ++ks) {
            unsigned a[2][4];
#pragma unroll
            for (int mt = 0; mt < 2; ++mt) {
                unsigned off = (a_row + mt * 16) * 128 + ks * 32 + a_kb;
                ldm_x4(a[mt][0], a[mt][1], a[mt][2], a[mt][3], Ab + SWZ(off));
            }
#pragma unroll
            for (int bi = 0; bi < NB; ++bi) {
                const unsigned Bb = sb + SM_B(s & 1, bi);
                unsigned bf[4];
                {
                    unsigned off = b_row * 128 + ks * 32 + b_kb;
                    ldm_x4(bf[0], bf[1], bf[2], bf[3], Bb + SWZ(off));
                }
#pragma unroll
                for (int mt = 0; mt < 2; ++mt)
#pragma unroll
                    for (int nt = 0; nt < 2; ++nt) {
                        mma16816(c[bi][mt][nt][0], c[bi][mt][nt][1],
                                 c[bi][mt][nt][2], c[bi][mt][nt][3],
                                 a[mt][0], a[mt][1], a[mt][2], a[mt][3],
                                 bf[nt * 2], bf[nt * 2 + 1]);
                    }
            }
        }
    }

    // ---- epilogue ----
    const int lq = lane >> 2, ln = (lane & 3) * 2;
#pragma unroll
    for (int bi = 0; bi < NB; ++bi) {
        const int b = jb[bi];
        float* ob = out + COMP_OFF + (size_t)b * L_ * V_;
        const int2 sel = g_sel[b];
        const float2 gg = g_gate[b];
#pragma unroll
        for (int mt = 0; mt < 2; ++mt) {
            int v0 = vbase + warp_m * 32 + mt * 16 + lq;
            int v1 = v0 + 8;
            float bias0 = 0.0f, bias1 = 0.0f;
            if (PASS == 0) {
                if (v0 < V_)
                    bias0 = gg.x * comp_b[(size_t)sel.x * V_ + v0] +
                            gg.y * comp_b[(size_t)sel.y * V_ + v0];
                if (v1 < V_)
                    bias1 = gg.x * comp_b[(size_t)sel.x * V_ + v1] +
                            gg.y * comp_b[(size_t)sel.y * V_ + v1];
            }
#pragma unroll
            for (int nt = 0; nt < 2; ++nt) {
                int l0 = warp_n * 16 + nt * 8 + ln;
                if (v0 < V_) {
                    float* p0 = &ob[(size_t)l0 * V_ + v0];
                    float* p1 = &ob[(size_t)(l0 + 1) * V_ + v0];
                    if (PASS == 0) {
                        p0[0] = c[bi][mt][nt][0] + bias0;
                        p1[0] = c[bi][mt][nt][1] + bias0;
                    } else {
                        p0[0] += c[bi][mt][nt][0];
                        p1[0] += c[bi][mt][nt][1];
                    }
                }
                if (v1 < V_) {
                    float* p2 = &ob[(size_t)l0 * V_ + v1];
                    float* p3 = &ob[(size_t)(l0 + 1) * V_ + v1];
                    if (PASS == 0) {
                        p2[0] = c[bi][mt][nt][2] + bias1;
                        p3[0] = c[bi][mt][nt][3] + bias1;
                    } else {
                        p2[0] += c[bi][mt][nt][2];
                        p3[0] += c[bi][mt][nt][3];
                    }
                }
            }
        }
    }
}

template <int PASS>
__global__ __launch_bounds__(512, 1)
void k_comp_mma(const float* __restrict__ comp_w,
                const float* __restrict__ comp_b,
                float* __restrict__ out) {
    const int job = blockIdx.x;
    const int nb = g_job_nb[PASS][job];
    if (nb == 0) return;
    extern __shared__ __align__(1024) char smem[];
    const unsigned sb = smem_u32(smem);
    const int vbase = blockIdx.y * 128;
    switch (nb) {
        case 4:  comp_body<4, PASS>(comp_w, comp_b, out, sb, job, vbase); break;
        case 3:  comp_body<3, PASS>(comp_w, comp_b, out, sb, job, vbase); break;
        case 2:  comp_body<2, PASS>(comp_w, comp_b, out, sb, job, vbase); break;
        default: comp_body<1, PASS>(comp_w, comp_b, out, sb, job, vbase); break;
    }
}

// ---------------------------------------------------------------------------
extern "C" void kernel_launch(void* const* d_in, const int* in_sizes, int n_in,
                              void* d_out, int out_size) {
    const float* q      = (const float*)d_in[0];
    const float* h      = (const float*)d_in[1];
    const float* gw1    = (const float*)d_in[2];
    const float* gb1    = (const float*)d_in[3];
    const float* gw2    = (const float*)d_in[4];
    const float* gb2    = (const float*)d_in[5];
    const float* gaussw = (const float*)d_in[6];
    const float* gaussb = (const float*)d_in[7];
    const float* compw  = (const float*)d_in[8];
    const float* compb  = (const float*)d_in[9];
    float* out = (float*)d_out;

    cudaFuncSetAttribute(k_comp_mma<0>, cudaFuncAttributeMaxDynamicSharedMemorySize,
                         SMEM_TOTAL);
    cudaFuncSetAttribute(k_comp_mma<1>, cudaFuncAttributeMaxDynamicSharedMemorySize,
                         SMEM_TOTAL);

    k_hid<<<dim3(B_, 4), 128>>>(q, gw1, gb1);                       // idx 0
    k_gate<<<1, 256>>>(gw2, gb2, out);                              // idx 1
    k_prep<<<dim3(B_, 2), 256>>>(h);                                // idx 2
    k_comp_mma<0><<<dim3(NJOBS, NVT), 512, SMEM_TOTAL>>>(compw, compb, out); // idx 3
    k_comp_mma<1><<<dim3(NJOBS, NVT), 512, SMEM_TOTAL>>>(compw, compb, out); // idx 4
    k_gauss<<<dim3(B_, OUT_), 64>>>(h, gaussw, gaussb, out);        // idx 5
}

// round 17
// speedup vs baseline: 1.1039x; 1.1039x over previous
#include <cuda_runtime.h>
#include <cuda_fp16.h>
#include <math.h>

#define B_ 32
#define L_ 64
#define H_ 1024
#define E_ 8
#define V_ 12000
#define OUT_ 16
#define HID_ 512
#define COMP_OFF 512                 // gauss_param occupies out[0:512]
#define LOSS_OFF (512 + 32*64*12000) // scalar at the end
#define NVT 94                       // ceil(12000/128)
#define NJOBS 22                     // max sum_e ceil(|S_e|/4), sum|S_e|=64

// -------------------- scratch (static device globals only) -----------------
__device__ float  g_hid[B_ * HID_];
__device__ int2   g_sel[B_];
__device__ float2 g_gate[B_];
__device__ __half g_h16[B_ * 2 * L_ * H_];   // [b][ei][l][k], gate pre-folded
// expert-grouped job table (built by k_gate thread 0)
__device__ int    g_job_e[NJOBS];
__device__ int    g_job_nb[NJOBS];
__device__ int    g_job_b[NJOBS * 4];
__device__ int    g_job_h[NJOBS * 4];        // index into g_h16 (b*2+ei)

// ===================== PTX helpers (all plain sm_80+ PTX) ==================
__device__ __forceinline__ unsigned smem_u32(const void* p) {
    unsigned a;
    asm("{ .reg .u64 t; cvta.to.shared.u64 t, %1; cvt.u32.u64 %0, t; }"
        : "=r"(a) : "l"(p));
    return a;
}
__device__ __forceinline__ void cp16(unsigned d, const void* s) {
    asm volatile("cp.async.cg.shared.global [%0], [%1], 16;"
                 :: "r"(d), "l"(s) : "memory");
}
__device__ __forceinline__ void sts128(unsigned a, unsigned x, unsigned y,
                                       unsigned z, unsigned w) {
    asm volatile("st.shared.v4.b32 [%0], {%1,%2,%3,%4};"
                 :: "r"(a), "r"(x), "r"(y), "r"(z), "r"(w) : "memory");
}
__device__ __forceinline__ void ldm_x4(unsigned& r0, unsigned& r1,
                                       unsigned& r2, unsigned& r3, unsigned a) {
    asm volatile("ldmatrix.sync.aligned.m8n8.x4.shared.b16 {%0,%1,%2,%3}, [%4];"
                 : "=r"(r0), "=r"(r1), "=r"(r2), "=r"(r3) : "r"(a));
}
__device__ __forceinline__ void mma16816(float& c0, float& c1, float& c2, float& c3,
                                         unsigned a0, unsigned a1, unsigned a2,
                                         unsigned a3, unsigned b0, unsigned b1) {
    asm volatile(
        "mma.sync.aligned.m16n8k16.row.col.f32.f16.f16.f32 "
        "{%0,%1,%2,%3}, {%4,%5,%6,%7}, {%8,%9}, {%0,%1,%2,%3};"
        : "+f"(c0), "+f"(c1), "+f"(c2), "+f"(c3)
        : "r"(a0), "r"(a1), "r"(a2), "r"(a3), "r"(b0), "r"(b1));
}
__device__ __forceinline__ unsigned h2u(__half2 h) {
    return *reinterpret_cast<unsigned*>(&h);
}
#define SWZ(o) ((o) ^ (((o) >> 3) & 0x70))

// SMEM: A = W f16 [128v x 64k] x2 buffers; B = h f16 [64l x 64k] x2 x 4 b's
#define SM_A0   0
#define SM_A1   16384
#define SM_B(buf, bb) (32768 + (buf) * 32768 + (bb) * 8192)
#define SMEM_TOTAL 98304

// -------------------- K1: hid = relu(q @ w1 + b1) --------------------------
__global__ void k_hid(const float* __restrict__ q,
                      const float* __restrict__ w1,
                      const float* __restrict__ b1) {
    __shared__ float qs[H_];
    int b = blockIdx.x;
    int j = blockIdx.y * 128 + threadIdx.x;
    for (int i = threadIdx.x; i < H_; i += 128) qs[i] = q[b * H_ + i];
    __syncthreads();
    float acc = b1[j];
#pragma unroll 8
    for (int i = 0; i < H_; ++i) acc = fmaf(qs[i], w1[i * HID_ + j], acc);
    g_hid[b * HID_ + j] = fmaxf(acc, 0.0f);
}

// -------- K2: logits, top-2 gates, moe_loss, expert-grouped job table ------
__global__ void k_gate(const float* __restrict__ w2,
                       const float* __restrict__ b2,
                       float* __restrict__ out) {
    __shared__ float w2s[HID_ * E_];
    __shared__ float lg[B_ * E_];
    __shared__ float gd[B_ * E_];
    __shared__ float imp[E_];
    int t = threadIdx.x;
    for (int i = t; i < HID_ * E_; i += 256) w2s[i] = w2[i];
    gd[t] = 0.0f;
    __syncthreads();
    {
        int b = t >> 3, e = t & 7;
        float acc = b2[e];
        const float* hb = &g_hid[b * HID_];
#pragma unroll 8
        for (int i = 0; i < HID_; ++i) acc = fmaf(hb[i], w2s[i * E_ + e], acc);
        lg[t] = acc;
    }
    __syncthreads();
    if (t < B_) {
        float v1 = -1e30f, v2 = -1e30f;
        int i1 = 0, i2 = 0;
        for (int e = 0; e < E_; ++e) {
            float v = lg[t * E_ + e];
            if (v > v1)      { v2 = v1; i2 = i1; v1 = v; i1 = e; }
            else if (v > v2) { v2 = v;  i2 = e; }
        }
        float ex = expf(v2 - v1);
        float s = 1.0f + ex;
        float g1 = 1.0f / s, g2 = ex / s;
        g_sel[t] = make_int2(i1, i2);
        g_gate[t] = make_float2(g1, g2);
        gd[t * E_ + i1] = g1;
        gd[t * E_ + i2] = g2;
    }
    __syncthreads();
    if (t < E_) {
        float s = 0.0f;
        for (int b = 0; b < B_; ++b) s += gd[b * E_ + t];
        imp[t] = s;
    }
    __syncthreads();
    if (t == 0) {
        float mean = 0.0f;
        for (int e = 0; e < E_; ++e) mean += imp[e];
        mean *= (1.0f / E_);
        float var = 0.0f;
        for (int e = 0; e < E_; ++e) { float d = imp[e] - mean; var += d * d; }
        var *= (1.0f / (E_ - 1));
        out[LOSS_OFF] = sqrtf(var) / (mean + 1e-10f) * 0.1f;

        // ---- build expert-grouped jobs (<=4 (b,ei) slots per job) ----
        int nj = 0;
        for (int e = 0; e < E_; ++e) {
            int cb[4], ch[4], cnt = 0;
            for (int b = 0; b < B_; ++b) {
                int2 sv = g_sel[b];
                int ei = (sv.x == e) ? 0 : ((sv.y == e) ? 1 : -1);
                if (ei < 0) continue;
                cb[cnt] = b; ch[cnt] = b * 2 + ei; ++cnt;
                if (cnt == 4) {
                    g_job_e[nj] = e; g_job_nb[nj] = 4;
                    for (int i2 = 0; i2 < 4; ++i2) {
                        g_job_b[nj * 4 + i2] = cb[i2];
                        g_job_h[nj * 4 + i2] = ch[i2];
                    }
                    ++nj; cnt = 0;
                }
            }
            if (cnt > 0) {
                g_job_e[nj] = e; g_job_nb[nj] = cnt;
                for (int i2 = 0; i2 < cnt; ++i2) {
                    g_job_b[nj * 4 + i2] = cb[i2];
                    g_job_h[nj * 4 + i2] = ch[i2];
                }
                ++nj;
            }
        }
        for (; nj < NJOBS; ++nj) g_job_nb[nj] = 0;
    }
}

// -------- K3 (fused): prep h16 | init comp bias | gauss ---------------------
// grid (B, 82): y<2 -> prescale h by gate into f16 (ei=y);
//               2<=y<66 -> write gated bias row l=y-2 of comp output;
//               y>=66 -> gauss output o=y-66.
__global__ void k_mid(const float* __restrict__ h,
                      const float* __restrict__ gw,
                      const float* __restrict__ gb,
                      const float* __restrict__ comp_b,
                      float* __restrict__ out) {
    __shared__ float part[2];
    const int b = blockIdx.x, y = blockIdx.y, t = threadIdx.x;
    const int2 sel = g_sel[b];
    const float2 gg = g_gate[b];

    if (y < 2) {                       // ---- prep: h * gate -> f16 ----
        const int ei = y;
        float g = ei ? gg.y : gg.x;
        const float4* src = (const float4*)(h + (size_t)b * L_ * H_);
        __half2* dst = (__half2*)(g_h16 + ((size_t)(b * 2 + ei)) * L_ * H_);
        for (int i = t; i < L_ * H_ / 4; i += 256) {
            float4 v = src[i];
            dst[2 * i + 0] = __floats2half2_rn(g * v.x, g * v.y);
            dst[2 * i + 1] = __floats2half2_rn(g * v.z, g * v.w);
        }
    } else if (y < 66) {               // ---- init: gated bias row ----
        const int l = y - 2;
        const float4* c1 = (const float4*)(comp_b + (size_t)sel.x * V_);
        const float4* c2 = (const float4*)(comp_b + (size_t)sel.y * V_);
        float4* o = (float4*)(out + COMP_OFF + ((size_t)b * L_ + l) * V_);
        for (int i = t; i < V_ / 4; i += 256) {
            float4 a = c1[i], d = c2[i], r;
            r.x = gg.x * a.x + gg.y * d.x;
            r.y = gg.x * a.y + gg.y * d.y;
            r.z = gg.x * a.z + gg.y * d.z;
            r.w = gg.x * a.w + gg.y * d.w;
            o[i] = r;
        }
    } else {                           // ---- gauss ----
        const int o = y - 66;
        const int w = t >> 5, l = t & 31;
        if (t < 64) {
            int e = w ? sel.y : sel.x;
            float g = w ? gg.y : gg.x;
            const float* hl = h + ((size_t)b * L_ + (L_ - 1)) * H_;
            const float* wp = gw + ((size_t)e * OUT_ + o) * H_;
            float a = 0.0f;
#pragma unroll 8
            for (int i = l; i < H_; i += 32) a = fmaf(hl[i], wp[i], a);
#pragma unroll
            for (int off = 16; off > 0; off >>= 1)
                a += __shfl_down_sync(0xffffffff, a, off);
            if (l == 0) part[w] = g * (a + gb[e * OUT_ + o]);
        }
        __syncthreads();
        if (t == 0) {
            float val = part[0] + part[1];
            out[b * OUT_ + o] = 1.0f / (1.0f + expf(-val));
        }
    }
}

// -------- K4: comp via expert-grouped HMMA jobs, 512 threads ---------------
// CTA(job, vtile): one expert's W tile [128v x 1024k] against NB<=4 slots'
// gate-folded h16 (N=64 each). 16 warps as 4(m) x 4(n); warp tile 32v x 16l
// per slot. W read ONCE chip-wide per vtile wave (all jobs concurrent in L2).
// Epilogue: atomicAdd into bias-initialized out.
template <int NB>
__device__ __forceinline__ void comp_body(const float* __restrict__ comp_w,
                                          float* __restrict__ out,
                                          unsigned sb, int job, int vbase) {
    const int t = threadIdx.x, wid = t >> 5, lane = t & 31;
    const int warp_m = wid >> 2, warp_n = wid & 3;
    const int e = g_job_e[job];

    int jh[NB], jb[NB];
#pragma unroll
    for (int bi = 0; bi < NB; ++bi) {
        jh[bi] = g_job_h[job * 4 + bi];
        jb[bi] = g_job_b[job * 4 + bi];
    }

    float c[NB][2][2][4];
#pragma unroll
    for (int bi = 0; bi < NB; ++bi)
#pragma unroll
        for (int i = 0; i < 2; ++i)
#pragma unroll
            for (int j = 0; j < 2; ++j)
#pragma unroll
                for (int k = 0; k < 4; ++k) c[bi][i][j][k] = 0.0f;

    // ---- prologue: cp.async h(0) for all NB (1 cp16/thread/slot) ----
#pragma unroll
    for (int bi = 0; bi < NB; ++bi) {
        const __half* src = g_h16 + (size_t)jh[bi] * L_ * H_;
        int r = t >> 3, cc = t & 7;
        cp16(sb + SM_B(0, bi) + SWZ(r * 128 + cc * 16), src + r * H_ + cc * 8);
    }
    asm volatile("cp.async.commit_group;" ::: "memory");

    const float* We = comp_w + (size_t)e * V_ * H_;
    float4 wreg[4];
#pragma unroll
    for (int j = 0; j < 2; ++j) {
        int tau = t + 512 * j, r = tau >> 3, cc = tau & 7;
        int v = vbase + r; if (v >= V_) v = V_ - 1;
        const float4* p = (const float4*)(We + (size_t)v * H_ + cc * 8);
        wreg[2 * j] = p[0]; wreg[2 * j + 1] = p[1];
    }

    const int a_row = warp_m * 32 + (lane & 7) + ((lane >> 3) & 1) * 8;
    const int a_kb  = ((lane >> 4) & 1) * 16;
    const int b_row = warp_n * 16 + (lane & 7) + ((lane >> 4) & 1) * 8;
    const int b_kb  = ((lane >> 3) & 1) * 16;

    for (int s = 0; s < 16; ++s) {
        const unsigned Ab = sb + ((s & 1) ? SM_A1 : SM_A0);

        asm volatile("cp.async.wait_group 0;" ::: "memory");

        // store W(s) as f16 (other buffer than compute(s-1) reads)
#pragma unroll
        for (int j = 0; j < 2; ++j) {
            int tau = t + 512 * j, r = tau >> 3, cc = tau & 7;
            __half2 h0 = __floats2half2_rn(wreg[2 * j].x,     wreg[2 * j].y);
            __half2 h1 = __floats2half2_rn(wreg[2 * j].z,     wreg[2 * j].w);
            __half2 h2 = __floats2half2_rn(wreg[2 * j + 1].x, wreg[2 * j + 1].y);
            __half2 h3 = __floats2half2_rn(wreg[2 * j + 1].z, wreg[2 * j + 1].w);
            sts128(Ab + SWZ(r * 128 + cc * 16), h2u(h0), h2u(h1), h2u(h2), h2u(h3));
        }

        if (s + 1 < 16) {
            int k0 = (s + 1) * 64;
#pragma unroll
            for (int j = 0; j < 2; ++j) {
                int tau = t + 512 * j, r = tau >> 3, cc = tau & 7;
                int v = vbase + r; if (v >= V_) v = V_ - 1;
                const float4* p = (const float4*)(We + (size_t)v * H_ + k0 + cc * 8);
                wreg[2 * j] = p[0]; wreg[2 * j + 1] = p[1];
            }
        }

        __syncthreads();

        if (s + 1 < 16) {
            int k0 = (s + 1) * 64, buf = (s + 1) & 1;
#pragma unroll
            for (int bi = 0; bi < NB; ++bi) {
                const __half* src = g_h16 + (size_t)jh[bi] * L_ * H_ + k0;
                int r = t >> 3, cc = t & 7;
                cp16(sb + SM_B(buf, bi) + SWZ(r * 128 + cc * 16),
                     src + r * H_ + cc * 8);
            }
            asm volatile("cp.async.commit_group;" ::: "memory");
        }

        // ---- compute: 4 k-steps; A ldm shared across all NB slots ----
#pragma unroll
        for (int ks = 0; ks < 4; ++ks) {
            unsigned a[2][4];
#pragma unroll
            for (int mt = 0; mt < 2; ++mt) {
                unsigned off = (a_row + mt * 16) * 128 + ks * 32 + a_kb;
                ldm_x4(a[mt][0], a[mt][1], a[mt][2], a[mt][3], Ab + SWZ(off));
            }
#pragma unroll
            for (int bi = 0; bi < NB; ++bi) {
                const unsigned Bb = sb + SM_B(s & 1, bi);
                unsigned bf[4];
                {
                    unsigned off = b_row * 128 + ks * 32 + b_kb;
                    ldm_x4(bf[0], bf[1], bf[2], bf[3], Bb + SWZ(off));
                }
#pragma unroll
                for (int mt = 0; mt < 2; ++mt)
#pragma unroll
                    for (int nt = 0; nt < 2; ++nt) {
                        mma16816(c[bi][mt][nt][0], c[bi][mt][nt][1],
                                 c[bi][mt][nt][2], c[bi][mt][nt][3],
                                 a[mt][0], a[mt][1], a[mt][2], a[mt][3],
                                 bf[nt * 2], bf[nt * 2 + 1]);
                    }
            }
        }
    }

    // ---- epilogue: atomicAdd into bias-initialized out ----
    const int lq = lane >> 2, ln = (lane & 3) * 2;
#pragma unroll
    for (int bi = 0; bi < NB; ++bi) {
        float* ob = out + COMP_OFF + (size_t)jb[bi] * L_ * V_;
#pragma unroll
        for (int mt = 0; mt < 2; ++mt) {
            int v0 = vbase + warp_m * 32 + mt * 16 + lq;
            int v1 = v0 + 8;
#pragma unroll
            for (int nt = 0; nt < 2; ++nt) {
                int l0 = warp_n * 16 + nt * 8 + ln;
                if (v0 < V_) {
                    atomicAdd(&ob[(size_t)l0 * V_ + v0],       c[bi][mt][nt][0]);
                    atomicAdd(&ob[(size_t)(l0 + 1) * V_ + v0], c[bi][mt][nt][1]);
                }
                if (v1 < V_) {
                    atomicAdd(&ob[(size_t)l0 * V_ + v1],       c[bi][mt][nt][2]);
                    atomicAdd(&ob[(size_t)(l0 + 1) * V_ + v1], c[bi][mt][nt][3]);
                }
            }
        }
    }
}

__global__ __launch_bounds__(512, 1)
void k_comp_mma(const float* __restrict__ comp_w,
                float* __restrict__ out) {
    const int job = blockIdx.x;
    const int nb = g_job_nb[job];
    if (nb == 0) return;
    extern __shared__ __align__(1024) char smem[];
    const unsigned sb = smem_u32(smem);
    const int vbase = blockIdx.y * 128;
    switch (nb) {
        case 4:  comp_body<4>(comp_w, out, sb, job, vbase); break;
        case 3:  comp_body<3>(comp_w, out, sb, job, vbase); break;
        case 2:  comp_body<2>(comp_w, out, sb, job, vbase); break;
        default: comp_body<1>(comp_w, out, sb, job, vbase); break;
    }
}

// ---------------------------------------------------------------------------
extern "C" void kernel_launch(void* const* d_in, const int* in_sizes, int n_in,
                              void* d_out, int out_size) {
    const float* q      = (const float*)d_in[0];
    const float* h      = (const float*)d_in[1];
    const float* gw1    = (const float*)d_in[2];
    const float* gb1    = (const float*)d_in[3];
    const float* gw2    = (const float*)d_in[4];
    const float* gb2    = (const float*)d_in[5];
    const float* gaussw = (const float*)d_in[6];
    const float* gaussb = (const float*)d_in[7];
    const float* compw  = (const float*)d_in[8];
    const float* compb  = (const float*)d_in[9];
    float* out = (float*)d_out;

    cudaFuncSetAttribute(k_comp_mma, cudaFuncAttributeMaxDynamicSharedMemorySize,
                         SMEM_TOTAL);

    k_hid<<<dim3(B_, 4), 128>>>(q, gw1, gb1);                       // idx 0
    k_gate<<<1, 256>>>(gw2, gb2, out);                              // idx 1
    k_mid<<<dim3(B_, 82), 256>>>(h, gaussw, gaussb, compb, out);    // idx 2
    k_comp_mma<<<dim3(NJOBS, NVT), 512, SMEM_TOTAL>>>(compw, out);  // idx 3
}